// round 1
// baseline (speedup 1.0000x reference)
#include <cuda_runtime.h>
#include <cuda_bf16.h>

#define N_NODES 50000
#define N_EDGES 1000000
#define H_DIM   128
#define OUT_DIM 64
#define N_RELS  16

// ---------------- scratch (device globals; no runtime allocation) ----------------
__device__ float g_X [N_NODES * H_DIM];                 // gathered input features
__device__ float g_W1[N_RELS * H_DIM * H_DIM];          // combined layer-1 weights
__device__ float g_W2[N_RELS * H_DIM * OUT_DIM];        // combined layer-2 weights
__device__ float g_Y1[(size_t)N_RELS * N_NODES * H_DIM];   // 409.6 MB
__device__ float g_Y2[(size_t)N_RELS * N_NODES * OUT_DIM]; // 204.8 MB
__device__ float g_h1[N_NODES * H_DIM];                 // layer-1 aggregate / layer-2 input

// ---------------- small utility kernels ----------------
__global__ void gather_x_kernel(const int* __restrict__ ids,
                                const float* __restrict__ emb) {
    int i = blockIdx.x * blockDim.x + threadIdx.x;   // over N_NODES*32 float4
    if (i < N_NODES * 32) {
        int node = i >> 5;
        int q    = i & 31;
        ((float4*)g_X)[i] = ((const float4*)emb)[(size_t)ids[node] * 32 + q];
    }
}

template <int OUTW>  // OUTW = H_DIM or OUT_DIM
__global__ void compute_W_kernel(const float* __restrict__ comp,
                                 const float* __restrict__ V) {
    // W[r, j] = sum_b comp[r,b] * V[b, j],  j over H_DIM*OUTW
    const int sz = H_DIM * OUTW;
    int j = blockIdx.x * blockDim.x + threadIdx.x;
    int r = blockIdx.y;
    if (j < sz) {
        float acc = 0.f;
        #pragma unroll
        for (int b = 0; b < N_RELS; b++)
            acc += comp[r * N_RELS + b] * V[(size_t)b * sz + j];
        float* W = (OUTW == H_DIM) ? g_W1 : g_W2;
        W[(size_t)r * sz + j] = acc;
    }
}

template <int LAYER>
__global__ void zero_kernel(float* __restrict__ out_ext) {
    // LAYER==1: zero g_h1 (N_NODES*H_DIM). LAYER==2: zero out_ext (N_NODES*OUT_DIM).
    const int n4 = (LAYER == 1) ? (N_NODES * H_DIM / 4) : (N_NODES * OUT_DIM / 4);
    float* p = (LAYER == 1) ? g_h1 : out_ext;
    int i = blockIdx.x * blockDim.x + threadIdx.x;
    if (i < n4)
        ((float4*)p)[i] = make_float4(0.f, 0.f, 0.f, 0.f);
}

// ---------------- per-relation dense GEMM: Y[r] = X @ W[r] ----------------
// BM=128 nodes, BN = full output width (128 or 64), BK=8, 256 threads,
// 8 x TN register tile per thread.
template <int LAYER>
__global__ __launch_bounds__(256, 2) void gemm_rel_kernel() {
    constexpr int BM = 128;
    constexpr int BK = 8;
    constexpr int BN = (LAYER == 1) ? 128 : 64;
    constexpr int TN = (LAYER == 1) ? 8 : 4;

    __shared__ float As[BK][BM];
    __shared__ float Bs[BK][BN];

    const float* __restrict__ Xp = (LAYER == 1) ? g_X : g_h1;
    const float* __restrict__ Wp =
        ((LAYER == 1) ? g_W1 : g_W2) + (size_t)blockIdx.y * H_DIM * BN;
    float* __restrict__ Yp =
        ((LAYER == 1) ? g_Y1 : g_Y2) + (size_t)blockIdx.y * N_NODES * BN;

    const int m0  = blockIdx.x * BM;
    const int tid = threadIdx.x;
    const int tx  = tid & 15;   // n direction (16)
    const int ty  = tid >> 4;   // m direction (16)

    const int aRow = tid >> 1;          // 0..127
    const int aCol = tid & 1;           // 0..1  (float4 along k)
    const int bRow = tid / (BN / 4);    // k row
    const int bCol = tid % (BN / 4);    // float4 along n

    float acc[8][TN];
    #pragma unroll
    for (int i = 0; i < 8; i++)
        #pragma unroll
        for (int j = 0; j < TN; j++) acc[i][j] = 0.f;

    for (int k0 = 0; k0 < H_DIM; k0 += BK) {
        // load A tile (transposed into As[k][m])
        int gm = m0 + aRow;
        float4 av = make_float4(0.f, 0.f, 0.f, 0.f);
        if (gm < N_NODES)
            av = *(const float4*)(Xp + (size_t)gm * H_DIM + k0 + aCol * 4);
        As[aCol * 4 + 0][aRow] = av.x;
        As[aCol * 4 + 1][aRow] = av.y;
        As[aCol * 4 + 2][aRow] = av.z;
        As[aCol * 4 + 3][aRow] = av.w;

        // load B tile (natural orientation Bs[k][n])
        if (BN == 128 || bRow < BK) {
            *(float4*)&Bs[bRow][bCol * 4] =
                *(const float4*)(Wp + (size_t)(k0 + bRow) * BN + bCol * 4);
        }
        __syncthreads();

        #pragma unroll
        for (int kk = 0; kk < BK; kk++) {
            float a[8];
            float4 a0 = *(const float4*)&As[kk][ty * 8];
            float4 a1 = *(const float4*)&As[kk][ty * 8 + 4];
            a[0] = a0.x; a[1] = a0.y; a[2] = a0.z; a[3] = a0.w;
            a[4] = a1.x; a[5] = a1.y; a[6] = a1.z; a[7] = a1.w;
            float b[TN];
            #pragma unroll
            for (int j = 0; j < TN; j += 4) {
                float4 bv = *(const float4*)&Bs[kk][tx * TN + j];
                b[j + 0] = bv.x; b[j + 1] = bv.y; b[j + 2] = bv.z; b[j + 3] = bv.w;
            }
            #pragma unroll
            for (int i = 0; i < 8; i++)
                #pragma unroll
                for (int j = 0; j < TN; j++)
                    acc[i][j] += a[i] * b[j];
        }
        __syncthreads();
    }

    // store
    #pragma unroll
    for (int i = 0; i < 8; i++) {
        int gm = m0 + ty * 8 + i;
        if (gm < N_NODES) {
            float* o = Yp + (size_t)gm * BN + tx * TN;
            #pragma unroll
            for (int j = 0; j < TN; j += 4)
                *(float4*)(o + j) =
                    make_float4(acc[i][j], acc[i][j + 1], acc[i][j + 2], acc[i][j + 3]);
        }
    }
}

// ---------------- edge scatter: out[dst] += norm * Y[etype, src] ----------------
__device__ __forceinline__ void red_add_v4(float* p, float4 v) {
    asm volatile("red.global.add.v4.f32 [%0], {%1, %2, %3, %4};"
                 :: "l"(p), "f"(v.x), "f"(v.y), "f"(v.z), "f"(v.w)
                 : "memory");
}
__device__ __forceinline__ void red_add_v2(float* p, float2 v) {
    asm volatile("red.global.add.v2.f32 [%0], {%1, %2};"
                 :: "l"(p), "f"(v.x), "f"(v.y)
                 : "memory");
}

template <int LAYER>
__global__ void scatter_kernel(const int* __restrict__ etype,
                               const int* __restrict__ src,
                               const int* __restrict__ dst,
                               const float* __restrict__ norm,
                               float* __restrict__ out_ext) {
    // one warp per edge
    int e    = (blockIdx.x * blockDim.x + threadIdx.x) >> 5;
    int lane = threadIdx.x & 31;
    if (e >= N_EDGES) return;

    int   r  = etype[e];
    int   s  = src[e];
    int   d  = dst[e];
    float nm = norm[e];

    if (LAYER == 1) {
        const float4* row =
            (const float4*)(g_Y1 + ((size_t)r * N_NODES + s) * H_DIM);
        float4 v = row[lane];
        v.x *= nm; v.y *= nm; v.z *= nm; v.w *= nm;
        red_add_v4(g_h1 + (size_t)d * H_DIM + lane * 4, v);
    } else {
        const float2* row =
            (const float2*)(g_Y2 + ((size_t)r * N_NODES + s) * OUT_DIM);
        float2 v = row[lane];
        v.x *= nm; v.y *= nm;
        red_add_v2(out_ext + (size_t)d * OUT_DIM + lane * 2, v);
    }
}

// ---------------- epilogues ----------------
__global__ void bias_relu_kernel(const float* __restrict__ bias1) {
    int i = blockIdx.x * blockDim.x + threadIdx.x;  // over N_NODES*32 float4
    if (i < N_NODES * 32) {
        int c4 = i & 31;
        float4 v = ((float4*)g_h1)[i];
        const float4 b = ((const float4*)bias1)[c4];
        v.x = fmaxf(v.x + b.x, 0.f);
        v.y = fmaxf(v.y + b.y, 0.f);
        v.z = fmaxf(v.z + b.z, 0.f);
        v.w = fmaxf(v.w + b.w, 0.f);
        ((float4*)g_h1)[i] = v;
    }
}

__global__ void bias2_kernel(const float* __restrict__ bias2,
                             float* __restrict__ out_ext) {
    int i = blockIdx.x * blockDim.x + threadIdx.x;  // over N_NODES*16 float4
    if (i < N_NODES * 16) {
        int c4 = i & 15;
        float4 v = ((float4*)out_ext)[i];
        const float4 b = ((const float4*)bias2)[c4];
        v.x += b.x; v.y += b.y; v.z += b.z; v.w += b.w;
        ((float4*)out_ext)[i] = v;
    }
}

// ---------------- launch ----------------
extern "C" void kernel_launch(void* const* d_in, const int* in_sizes, int n_in,
                              void* d_out, int out_size) {
    const int*   node_ids = (const int*)  d_in[0];
    const int*   src      = (const int*)  d_in[1];
    const int*   dst      = (const int*)  d_in[2];
    const int*   etype    = (const int*)  d_in[3];
    const float* norm     = (const float*)d_in[4];
    const float* emb      = (const float*)d_in[5];
    const float* V1       = (const float*)d_in[6];
    const float* comp1    = (const float*)d_in[7];
    const float* bias1    = (const float*)d_in[8];
    const float* V2       = (const float*)d_in[9];
    const float* comp2    = (const float*)d_in[10];
    const float* bias2    = (const float*)d_in[11];
    float*       out      = (float*)d_out;

    const int T = 256;

    // gather X = emb[node_ids]
    gather_x_kernel<<<(N_NODES * 32 + T - 1) / T, T>>>(node_ids, emb);

    // combine basis weights
    {
        dim3 g1((H_DIM * H_DIM + T - 1) / T, N_RELS);
        compute_W_kernel<H_DIM><<<g1, T>>>(comp1, V1);
        dim3 g2((H_DIM * OUT_DIM + T - 1) / T, N_RELS);
        compute_W_kernel<OUT_DIM><<<g2, T>>>(comp2, V2);
    }

    // ---- layer 1 ----
    zero_kernel<1><<<(N_NODES * H_DIM / 4 + T - 1) / T, T>>>(nullptr);
    {
        dim3 grid((N_NODES + 127) / 128, N_RELS);
        gemm_rel_kernel<1><<<grid, 256>>>();
    }
    {
        long long threads = (long long)N_EDGES * 32;
        scatter_kernel<1><<<(unsigned)((threads + T - 1) / T), T>>>(etype, src, dst, norm, nullptr);
    }
    bias_relu_kernel<<<(N_NODES * 32 + T - 1) / T, T>>>(bias1);

    // ---- layer 2 ----
    zero_kernel<2><<<(N_NODES * OUT_DIM / 4 + T - 1) / T, T>>>(out);
    {
        dim3 grid((N_NODES + 127) / 128, N_RELS);
        gemm_rel_kernel<2><<<grid, 256>>>();
    }
    {
        long long threads = (long long)N_EDGES * 32;
        scatter_kernel<2><<<(unsigned)((threads + T - 1) / T), T>>>(etype, src, dst, norm, out);
    }
    bias2_kernel<<<(N_NODES * 16 + T - 1) / T, T>>>(bias2, out);
}

// round 5
// speedup vs baseline: 1.0371x; 1.0371x over previous
#include <cuda_runtime.h>
#include <cuda_bf16.h>
#include <mma.h>
#include <cstdint>

using namespace nvcuda;

#define N_NODES 50000
#define N_PAD   50048   // 391 * 128 : full-tile padding for GEMM stores
#define N_EDGES 1000000
#define H_DIM   128
#define OUT_DIM 64
#define N_RELS  16

// ---------------- scratch (device globals; no runtime allocation) ----------------
__device__ __align__(256) float g_X [N_PAD * H_DIM];                 // gathered input (pad rows stay 0)
__device__ __align__(256) float g_W1[N_RELS * H_DIM * H_DIM];
__device__ __align__(256) float g_W2[N_RELS * H_DIM * OUT_DIM];
__device__ __align__(256) float g_Y1[(size_t)N_RELS * N_PAD * H_DIM];   // ~410 MB
__device__ __align__(256) float g_Y2[(size_t)N_RELS * N_PAD * OUT_DIM]; // ~205 MB
__device__ __align__(256) float g_h1[N_PAD * H_DIM];                 // pad rows stay 0

// ---------------- small utility kernels ----------------
__global__ void gather_x_kernel(const int* __restrict__ ids,
                                const float* __restrict__ emb) {
    int i = blockIdx.x * blockDim.x + threadIdx.x;   // over N_NODES*32 float4
    if (i < N_NODES * 32) {
        int node = i >> 5;
        int q    = i & 31;
        ((float4*)g_X)[(size_t)node * 32 + q] =
            ((const float4*)emb)[(size_t)ids[node] * 32 + q];
    }
}

template <int OUTW>
__global__ void compute_W_kernel(const float* __restrict__ comp,
                                 const float* __restrict__ V) {
    const int sz = H_DIM * OUTW;
    int j = blockIdx.x * blockDim.x + threadIdx.x;
    int r = blockIdx.y;
    if (j < sz) {
        float acc = 0.f;
        #pragma unroll
        for (int b = 0; b < N_RELS; b++)
            acc += comp[r * N_RELS + b] * V[(size_t)b * sz + j];
        float* W = (OUTW == H_DIM) ? g_W1 : g_W2;
        W[(size_t)r * sz + j] = acc;
    }
}

template <int LAYER>
__global__ void zero_kernel(float* __restrict__ out_ext) {
    const int n4 = (LAYER == 1) ? (N_NODES * H_DIM / 4) : (N_NODES * OUT_DIM / 4);
    float* p = (LAYER == 1) ? g_h1 : out_ext;
    int i = blockIdx.x * blockDim.x + threadIdx.x;
    if (i < n4)
        ((float4*)p)[i] = make_float4(0.f, 0.f, 0.f, 0.f);
}

// ---------------- wmma bf16 split-precision GEMM: Y[r] = X @ W[r] ----------------
// X = Xhi + Xlo (bf16 each), W = Whi + Wlo.
// acc += Xhi*Whi + Xhi*Wlo + Xlo*Whi   (fp32 accum; lo*lo dropped, ~2^-18 rel)
// Tile: BM=128, BN=(128|64), K=128 fully resident in smem.
// 256 threads = 8 warps laid out 4(m) x 2(n); per warp 32 x BN/2.
template <int LAYER>
__global__ __launch_bounds__(256, 1) void gemm_wmma_kernel() {
    constexpr int BN = (LAYER == 1) ? 128 : 64;
    constexpr int AP = 136;        // a smem pitch (halves)
    constexpr int BP = BN + 8;     // b smem pitch (halves)
    constexpr int NF = BN / 2 / 16;  // n-fragments per warp (4 | 2)

    extern __shared__ __nv_bfloat16 sm[];
    __nv_bfloat16* a_hi = sm;
    __nv_bfloat16* a_lo = a_hi + 128 * AP;
    __nv_bfloat16* b_hi = a_lo + 128 * AP;
    __nv_bfloat16* b_lo = b_hi + 128 * BP;

    const int tid = threadIdx.x;
    const int rel = blockIdx.y;
    const int m0  = blockIdx.x * 128;

    const float* __restrict__ Xp = (LAYER == 1) ? g_X : g_h1;
    const float* __restrict__ Wp =
        ((LAYER == 1) ? g_W1 : g_W2) + (size_t)rel * H_DIM * BN;
    float* __restrict__ Yp =
        ((LAYER == 1) ? g_Y1 : g_Y2) + (size_t)rel * N_PAD * BN;

    // ---- load + split A tile: X[m0 .. m0+128, 0:128] (always in bounds: N_PAD) ----
    for (int i = tid; i < 128 * 32; i += 256) {
        int row = i >> 5, c4 = i & 31;
        float4 v = *(const float4*)(Xp + (size_t)(m0 + row) * H_DIM + c4 * 4);
        float vv[4] = {v.x, v.y, v.z, v.w};
        #pragma unroll
        for (int j = 0; j < 4; j++) {
            __nv_bfloat16 h = __float2bfloat16(vv[j]);
            __nv_bfloat16 l = __float2bfloat16(vv[j] - __bfloat162float(h));
            a_hi[row * AP + c4 * 4 + j] = h;
            a_lo[row * AP + c4 * 4 + j] = l;
        }
    }
    // ---- load + split B tile: W[k][n], natural row-major [k][n] ----
    for (int i = tid; i < 128 * BN / 4; i += 256) {
        int k = i / (BN / 4);
        int n = (i % (BN / 4)) * 4;
        float4 v = *(const float4*)(Wp + (size_t)k * BN + n);
        float vv[4] = {v.x, v.y, v.z, v.w};
        #pragma unroll
        for (int j = 0; j < 4; j++) {
            __nv_bfloat16 h = __float2bfloat16(vv[j]);
            __nv_bfloat16 l = __float2bfloat16(vv[j] - __bfloat162float(h));
            b_hi[k * BP + n + j] = h;
            b_lo[k * BP + n + j] = l;
        }
    }
    __syncthreads();

    const int wid = tid >> 5;
    const int wm  = wid & 3;        // 0..3  -> m offset wm*32
    const int wn  = wid >> 2;       // 0..1  -> n offset wn*(BN/2)

    wmma::fragment<wmma::accumulator, 16, 16, 16, float> acc[2][NF];
    #pragma unroll
    for (int i = 0; i < 2; i++)
        #pragma unroll
        for (int j = 0; j < NF; j++)
            wmma::fill_fragment(acc[i][j], 0.f);

    #pragma unroll
    for (int k0 = 0; k0 < 128; k0 += 16) {
        wmma::fragment<wmma::matrix_a, 16, 16, 16, __nv_bfloat16, wmma::row_major> ah[2], al[2];
        #pragma unroll
        for (int i = 0; i < 2; i++) {
            wmma::load_matrix_sync(ah[i], a_hi + (wm * 32 + i * 16) * AP + k0, AP);
            wmma::load_matrix_sync(al[i], a_lo + (wm * 32 + i * 16) * AP + k0, AP);
        }
        #pragma unroll
        for (int j = 0; j < NF; j++) {
            wmma::fragment<wmma::matrix_b, 16, 16, 16, __nv_bfloat16, wmma::row_major> bh, bl;
            wmma::load_matrix_sync(bh, b_hi + k0 * BP + wn * (BN / 2) + j * 16, BP);
            wmma::load_matrix_sync(bl, b_lo + k0 * BP + wn * (BN / 2) + j * 16, BP);
            #pragma unroll
            for (int i = 0; i < 2; i++) {
                wmma::mma_sync(acc[i][j], ah[i], bh, acc[i][j]);
                wmma::mma_sync(acc[i][j], ah[i], bl, acc[i][j]);
                wmma::mma_sync(acc[i][j], al[i], bh, acc[i][j]);
            }
        }
    }

    // ---- store (unguarded: Y is padded to N_PAD rows) ----
    #pragma unroll
    for (int i = 0; i < 2; i++)
        #pragma unroll
        for (int j = 0; j < NF; j++)
            wmma::store_matrix_sync(
                Yp + (size_t)(m0 + wm * 32 + i * 16) * BN + wn * (BN / 2) + j * 16,
                acc[i][j], BN, wmma::mem_row_major);
}

// ---------------- edge scatter: out[dst] += norm * Y[etype, src] ----------------
__device__ __forceinline__ void red_add_v4(float* p, float4 v) {
    asm volatile("red.global.add.v4.f32 [%0], {%1, %2, %3, %4};"
                 :: "l"(p), "f"(v.x), "f"(v.y), "f"(v.z), "f"(v.w) : "memory");
}
__device__ __forceinline__ void red_add_v2(float* p, float2 v) {
    asm volatile("red.global.add.v2.f32 [%0], {%1, %2};"
                 :: "l"(p), "f"(v.x), "f"(v.y) : "memory");
}

template <int LAYER>
__global__ void scatter_kernel(const int* __restrict__ etype,
                               const int* __restrict__ src,
                               const int* __restrict__ dst,
                               const float* __restrict__ norm,
                               float* __restrict__ out_ext) {
    int e    = (blockIdx.x * blockDim.x + threadIdx.x) >> 5;
    int lane = threadIdx.x & 31;
    if (e >= N_EDGES) return;

    int   r  = etype[e];
    int   s  = src[e];
    int   d  = dst[e];
    float nm = norm[e];

    if (LAYER == 1) {
        const float4* row = (const float4*)(g_Y1 + ((size_t)r * N_PAD + s) * H_DIM);
        float4 v = row[lane];
        v.x *= nm; v.y *= nm; v.z *= nm; v.w *= nm;
        red_add_v4(g_h1 + (size_t)d * H_DIM + lane * 4, v);
    } else {
        const float2* row = (const float2*)(g_Y2 + ((size_t)r * N_PAD + s) * OUT_DIM);
        float2 v = row[lane];
        v.x *= nm; v.y *= nm;
        red_add_v2(out_ext + (size_t)d * OUT_DIM + lane * 2, v);
    }
}

// ---------------- epilogues ----------------
__global__ void bias_relu_kernel(const float* __restrict__ bias1) {
    int i = blockIdx.x * blockDim.x + threadIdx.x;
    if (i < N_NODES * 32) {
        int c4 = i & 31;
        float4 v = ((float4*)g_h1)[i];
        const float4 b = ((const float4*)bias1)[c4];
        v.x = fmaxf(v.x + b.x, 0.f);
        v.y = fmaxf(v.y + b.y, 0.f);
        v.z = fmaxf(v.z + b.z, 0.f);
        v.w = fmaxf(v.w + b.w, 0.f);
        ((float4*)g_h1)[i] = v;
    }
}

__global__ void bias2_kernel(const float* __restrict__ bias2,
                             float* __restrict__ out_ext) {
    int i = blockIdx.x * blockDim.x + threadIdx.x;
    if (i < N_NODES * 16) {
        int c4 = i & 15;
        float4 v = ((float4*)out_ext)[i];
        const float4 b = ((const float4*)bias2)[c4];
        v.x += b.x; v.y += b.y; v.z += b.z; v.w += b.w;
        ((float4*)out_ext)[i] = v;
    }
}

// ---------------- launch ----------------
extern "C" void kernel_launch(void* const* d_in, const int* in_sizes, int n_in,
                              void* d_out, int out_size) {
    const int*   node_ids = (const int*)  d_in[0];
    const int*   src      = (const int*)  d_in[1];
    const int*   dst      = (const int*)  d_in[2];
    const int*   etype    = (const int*)  d_in[3];
    const float* norm     = (const float*)d_in[4];
    const float* emb      = (const float*)d_in[5];
    const float* V1       = (const float*)d_in[6];
    const float* comp1    = (const float*)d_in[7];
    const float* bias1    = (const float*)d_in[8];
    const float* V2       = (const float*)d_in[9];
    const float* comp2    = (const float*)d_in[10];
    const float* bias2    = (const float*)d_in[11];
    float*       out      = (float*)d_out;

    const int T = 256;
    // dyn smem (bytes): L1: (2*128*136 + 2*128*136) * 2 = 139264
    //                   L2: (2*128*136 + 2*128*72)  * 2 = 106496
    const int SMEM1 = (2 * 128 * 136 + 2 * 128 * (128 + 8)) * 2;
    const int SMEM2 = (2 * 128 * 136 + 2 * 128 * (64 + 8)) * 2;
    cudaFuncSetAttribute(gemm_wmma_kernel<1>, cudaFuncAttributeMaxDynamicSharedMemorySize, SMEM1);
    cudaFuncSetAttribute(gemm_wmma_kernel<2>, cudaFuncAttributeMaxDynamicSharedMemorySize, SMEM2);

    // gather X = emb[node_ids]
    gather_x_kernel<<<(N_NODES * 32 + T - 1) / T, T>>>(node_ids, emb);

    // combine basis weights
    {
        dim3 g1((H_DIM * H_DIM + T - 1) / T, N_RELS);
        compute_W_kernel<H_DIM><<<g1, T>>>(comp1, V1);
        dim3 g2((H_DIM * OUT_DIM + T - 1) / T, N_RELS);
        compute_W_kernel<OUT_DIM><<<g2, T>>>(comp2, V2);
    }

    // ---- layer 1 ----
    zero_kernel<1><<<(N_NODES * H_DIM / 4 + T - 1) / T, T>>>(nullptr);
    {
        dim3 grid(N_PAD / 128, N_RELS);
        gemm_wmma_kernel<1><<<grid, 256, SMEM1>>>();
    }
    {
        long long threads = (long long)N_EDGES * 32;
        scatter_kernel<1><<<(unsigned)((threads + T - 1) / T), T>>>(etype, src, dst, norm, nullptr);
    }
    bias_relu_kernel<<<(N_NODES * 32 + T - 1) / T, T>>>(bias1);

    // ---- layer 2 ----
    zero_kernel<2><<<(N_NODES * OUT_DIM / 4 + T - 1) / T, T>>>(out);
    {
        dim3 grid(N_PAD / 128, N_RELS);
        gemm_wmma_kernel<2><<<grid, 256, SMEM2>>>();
    }
    {
        long long threads = (long long)N_EDGES * 32;
        scatter_kernel<2><<<(unsigned)((threads + T - 1) / T), T>>>(etype, src, dst, norm, out);
    }
    bias2_kernel<<<(N_NODES * 16 + T - 1) / T, T>>>(bias2, out);
}

// round 6
// speedup vs baseline: 2.1869x; 2.1087x over previous
#include <cuda_runtime.h>
#include <cuda_fp16.h>
#include <mma.h>
#include <cstdint>

using namespace nvcuda;

#define N_NODES 50000
#define N_PAD   50048   // 391 * 128 : full-tile padding for GEMM
#define N_EDGES 1000000
#define H_DIM   128
#define OUT_DIM 64
#define N_RELS  16
#define WSCALE  16.0f   // W pre-scaled so fp16 lo-part stays in normal range

// ---------------- scratch (device globals; no runtime allocation) ----------------
__device__ __align__(256) __half g_Xh [N_PAD * H_DIM];               // fp16 x (pad rows BSS-zero, never written)
__device__ __align__(256) __half g_W1h[N_RELS * H_DIM * H_DIM];      // 16*W1 hi
__device__ __align__(256) __half g_W1l[N_RELS * H_DIM * H_DIM];      // 16*W1 lo
__device__ __align__(256) __half g_W2h[N_RELS * H_DIM * OUT_DIM];
__device__ __align__(256) __half g_W2l[N_RELS * H_DIM * OUT_DIM];
__device__ __align__(256) __half g_Y1h[(size_t)N_RELS * N_PAD * H_DIM];   // ~205 MB (16x scaled)
__device__ __align__(256) __half g_Y2h[(size_t)N_RELS * N_PAD * OUT_DIM]; // ~102 MB (16x scaled)
__device__ __align__(256) float  g_h1 [N_PAD * H_DIM];               // fp32 atomic target (pads BSS-zero)
__device__ __align__(256) __half g_h1h[N_PAD * H_DIM];               // fp16 copy for GEMM2 (pads BSS-zero)

// ---------------- small utility kernels ----------------
__global__ void gather_x_kernel(const int* __restrict__ ids,
                                const float* __restrict__ emb) {
    int i = blockIdx.x * blockDim.x + threadIdx.x;   // over N_NODES*16 uint4 (8 halves)
    if (i < N_NODES * 16) {
        int node = i >> 4;
        int c8   = i & 15;
        const float4* e4 = (const float4*)(emb + (size_t)ids[node] * H_DIM);
        float4 f0 = e4[c8 * 2], f1 = e4[c8 * 2 + 1];
        __half2 h[4];
        h[0] = __floats2half2_rn(f0.x, f0.y);
        h[1] = __floats2half2_rn(f0.z, f0.w);
        h[2] = __floats2half2_rn(f1.x, f1.y);
        h[3] = __floats2half2_rn(f1.z, f1.w);
        ((uint4*)g_Xh)[(size_t)node * 16 + c8] = *(uint4*)h;
    }
}

template <int OUTW>
__global__ void compute_W_kernel(const float* __restrict__ comp,
                                 const float* __restrict__ V) {
    const int sz = H_DIM * OUTW;
    int j = blockIdx.x * blockDim.x + threadIdx.x;
    int r = blockIdx.y;
    if (j < sz) {
        float acc = 0.f;
        #pragma unroll
        for (int b = 0; b < N_RELS; b++)
            acc += comp[r * N_RELS + b] * V[(size_t)b * sz + j];
        acc *= WSCALE;
        __half hi = __float2half(acc);
        __half lo = __float2half(acc - __half2float(hi));
        __half* Wh = (OUTW == H_DIM) ? g_W1h : g_W2h;
        __half* Wl = (OUTW == H_DIM) ? g_W1l : g_W2l;
        Wh[(size_t)r * sz + j] = hi;
        Wl[(size_t)r * sz + j] = lo;
    }
}

template <int LAYER>
__global__ void zero_kernel(float* __restrict__ out_ext) {
    const int n4 = (LAYER == 1) ? (N_NODES * H_DIM / 4) : (N_NODES * OUT_DIM / 4);
    float* p = (LAYER == 1) ? g_h1 : out_ext;
    int i = blockIdx.x * blockDim.x + threadIdx.x;
    if (i < n4)
        ((float4*)p)[i] = make_float4(0.f, 0.f, 0.f, 0.f);
}

// ---------------- wmma fp16 2-pass GEMM: Y[r] = X @ (Whi[r] + Wlo[r]) ----------------
// A (X or h1) single fp16; W split hi+lo fp16 (22-bit effective, pre-scaled x16).
// acc(fp32) += A*Bhi + A*Blo. Y stored fp16 (16x scaled; scatter divides back).
// Tile: BM=128, BN=(128|64), K=128 resident. 8 warps: 4(m) x 2(n).
template <int LAYER>
__global__ __launch_bounds__(256, 2) void gemm_wmma_kernel() {
    constexpr int BN = (LAYER == 1) ? 128 : 64;
    constexpr int AP = 136;           // A smem pitch (halves)
    constexpr int BP = BN + 8;        // B smem pitch (halves)
    constexpr int NF = BN / 2 / 16;   // n-frags per warp (4 | 2)
    constexpr int NU4 = BN / 8;       // uint4 per B row

    extern __shared__ __half sm[];
    __half* a_s = sm;
    __half* bh_s = a_s + 128 * AP;
    __half* bl_s = bh_s + 128 * BP;

    const int tid = threadIdx.x;
    const int rel = blockIdx.y;
    const int m0  = blockIdx.x * 128;

    const __half* __restrict__ Ap = (LAYER == 1) ? g_Xh : g_h1h;
    const __half* __restrict__ Wh =
        ((LAYER == 1) ? g_W1h : g_W2h) + (size_t)rel * H_DIM * BN;
    const __half* __restrict__ Wl =
        ((LAYER == 1) ? g_W1l : g_W2l) + (size_t)rel * H_DIM * BN;
    __half* __restrict__ Yp =
        ((LAYER == 1) ? g_Y1h : g_Y2h) + (size_t)rel * N_PAD * BN;

    // ---- load A tile (always in bounds: N_PAD padding) ----
    #pragma unroll
    for (int i = tid; i < 128 * 16; i += 256) {
        int row = i >> 4, c8 = i & 15;
        *(uint4*)(a_s + row * AP + c8 * 8) =
            *(const uint4*)(Ap + (size_t)(m0 + row) * H_DIM + c8 * 8);
    }
    // ---- load B hi/lo tiles ----
    #pragma unroll
    for (int i = tid; i < 128 * NU4; i += 256) {
        int row = i / NU4, c = (i % NU4) * 8;
        *(uint4*)(bh_s + row * BP + c) = *(const uint4*)(Wh + (size_t)row * BN + c);
        *(uint4*)(bl_s + row * BP + c) = *(const uint4*)(Wl + (size_t)row * BN + c);
    }
    __syncthreads();

    const int wid = tid >> 5;
    const int wm  = wid & 3;      // m offset wm*32
    const int wn  = wid >> 2;     // n offset wn*(BN/2)

    wmma::fragment<wmma::accumulator, 16, 16, 16, float> acc[2][NF];
    #pragma unroll
    for (int i = 0; i < 2; i++)
        #pragma unroll
        for (int j = 0; j < NF; j++)
            wmma::fill_fragment(acc[i][j], 0.f);

    #pragma unroll
    for (int k0 = 0; k0 < 128; k0 += 16) {
        wmma::fragment<wmma::matrix_a, 16, 16, 16, __half, wmma::row_major> af[2];
        #pragma unroll
        for (int i = 0; i < 2; i++)
            wmma::load_matrix_sync(af[i], a_s + (wm * 32 + i * 16) * AP + k0, AP);
        #pragma unroll
        for (int j = 0; j < NF; j++) {
            wmma::fragment<wmma::matrix_b, 16, 16, 16, __half, wmma::row_major> bh, bl;
            wmma::load_matrix_sync(bh, bh_s + k0 * BP + wn * (BN / 2) + j * 16, BP);
            wmma::load_matrix_sync(bl, bl_s + k0 * BP + wn * (BN / 2) + j * 16, BP);
            #pragma unroll
            for (int i = 0; i < 2; i++) {
                wmma::mma_sync(acc[i][j], af[i], bh, acc[i][j]);
                wmma::mma_sync(acc[i][j], af[i], bl, acc[i][j]);
            }
        }
    }

    // ---- store fp16 (unguarded: N_PAD rows) ----
    #pragma unroll
    for (int i = 0; i < 2; i++)
        #pragma unroll
        for (int j = 0; j < NF; j++) {
            wmma::fragment<wmma::accumulator, 16, 16, 16, __half> hacc;
            #pragma unroll
            for (int e = 0; e < hacc.num_elements; e++)
                hacc.x[e] = __float2half(acc[i][j].x[e]);
            wmma::store_matrix_sync(
                Yp + (size_t)(m0 + wm * 32 + i * 16) * BN + wn * (BN / 2) + j * 16,
                hacc, BN, wmma::mem_row_major);
        }
}

// ---------------- edge scatter: out[dst] += (norm/16) * Y[etype, src] ----------------
__device__ __forceinline__ void red_add_v4(float* p, float4 v) {
    asm volatile("red.global.add.v4.f32 [%0], {%1, %2, %3, %4};"
                 :: "l"(p), "f"(v.x), "f"(v.y), "f"(v.z), "f"(v.w) : "memory");
}
__device__ __forceinline__ void red_add_v2(float* p, float2 v) {
    asm volatile("red.global.add.v2.f32 [%0], {%1, %2};"
                 :: "l"(p), "f"(v.x), "f"(v.y) : "memory");
}

template <int LAYER>
__global__ void scatter_kernel(const int* __restrict__ etype,
                               const int* __restrict__ src,
                               const int* __restrict__ dst,
                               const float* __restrict__ norm,
                               float* __restrict__ out_ext) {
    int e    = (blockIdx.x * blockDim.x + threadIdx.x) >> 5;
    int lane = threadIdx.x & 31;
    if (e >= N_EDGES) return;

    int   r  = etype[e];
    int   s  = src[e];
    int   d  = dst[e];
    float nm = norm[e] * (1.0f / WSCALE);

    if (LAYER == 1) {
        uint2 v = ((const uint2*)(g_Y1h + ((size_t)r * N_PAD + s) * H_DIM))[lane];
        float2 f0 = __half22float2(*(__half2*)&v.x);
        float2 f1 = __half22float2(*(__half2*)&v.y);
        red_add_v4(g_h1 + (size_t)d * H_DIM + lane * 4,
                   make_float4(f0.x * nm, f0.y * nm, f1.x * nm, f1.y * nm));
    } else {
        uint32_t v = ((const uint32_t*)(g_Y2h + ((size_t)r * N_PAD + s) * OUT_DIM))[lane];
        float2 f = __half22float2(*(__half2*)&v);
        red_add_v2(out_ext + (size_t)d * OUT_DIM + lane * 2,
                   make_float2(f.x * nm, f.y * nm));
    }
}

// ---------------- epilogues ----------------
__global__ void bias_relu_kernel(const float* __restrict__ bias1) {
    int i = blockIdx.x * blockDim.x + threadIdx.x;  // over N_NODES*32 float4
    if (i < N_NODES * 32) {
        int c4 = i & 31;
        float4 v = ((float4*)g_h1)[i];
        const float4 b = ((const float4*)bias1)[c4];
        v.x = fmaxf(v.x + b.x, 0.f);
        v.y = fmaxf(v.y + b.y, 0.f);
        v.z = fmaxf(v.z + b.z, 0.f);
        v.w = fmaxf(v.w + b.w, 0.f);
        ((float4*)g_h1)[i] = v;
        __half2 h0 = __floats2half2_rn(v.x, v.y);
        __half2 h1v = __floats2half2_rn(v.z, v.w);
        ((uint2*)g_h1h)[i] = make_uint2(*(uint32_t*)&h0, *(uint32_t*)&h1v);
    }
}

__global__ void bias2_kernel(const float* __restrict__ bias2,
                             float* __restrict__ out_ext) {
    int i = blockIdx.x * blockDim.x + threadIdx.x;
    if (i < N_NODES * 16) {
        int c4 = i & 15;
        float4 v = ((float4*)out_ext)[i];
        const float4 b = ((const float4*)bias2)[c4];
        v.x += b.x; v.y += b.y; v.z += b.z; v.w += b.w;
        ((float4*)out_ext)[i] = v;
    }
}

// ---------------- launch ----------------
extern "C" void kernel_launch(void* const* d_in, const int* in_sizes, int n_in,
                              void* d_out, int out_size) {
    const int*   node_ids = (const int*)  d_in[0];
    const int*   src      = (const int*)  d_in[1];
    const int*   dst      = (const int*)  d_in[2];
    const int*   etype    = (const int*)  d_in[3];
    const float* norm     = (const float*)d_in[4];
    const float* emb      = (const float*)d_in[5];
    const float* V1       = (const float*)d_in[6];
    const float* comp1    = (const float*)d_in[7];
    const float* bias1    = (const float*)d_in[8];
    const float* V2       = (const float*)d_in[9];
    const float* comp2    = (const float*)d_in[10];
    const float* bias2    = (const float*)d_in[11];
    float*       out      = (float*)d_out;

    const int T = 256;
    // dyn smem (bytes): L1: (128*136 + 2*128*136)*2 = 104448 -> 2 CTA/SM
    //                   L2: (128*136 + 2*128*72)*2  = 71680  -> 3 CTA/SM
    const int SMEM1 = (128 * 136 + 2 * 128 * (128 + 8)) * 2;
    const int SMEM2 = (128 * 136 + 2 * 128 * (64 + 8)) * 2;
    cudaFuncSetAttribute(gemm_wmma_kernel<1>, cudaFuncAttributeMaxDynamicSharedMemorySize, SMEM1);
    cudaFuncSetAttribute(gemm_wmma_kernel<2>, cudaFuncAttributeMaxDynamicSharedMemorySize, SMEM2);

    // gather + fp16 convert X
    gather_x_kernel<<<(N_NODES * 16 + T - 1) / T, T>>>(node_ids, emb);

    // combine basis weights, split into fp16 hi/lo (scaled x16)
    {
        dim3 g1((H_DIM * H_DIM + T - 1) / T, N_RELS);
        compute_W_kernel<H_DIM><<<g1, T>>>(comp1, V1);
        dim3 g2((H_DIM * OUT_DIM + T - 1) / T, N_RELS);
        compute_W_kernel<OUT_DIM><<<g2, T>>>(comp2, V2);
    }

    // ---- layer 1 ----
    zero_kernel<1><<<(N_NODES * H_DIM / 4 + T - 1) / T, T>>>(nullptr);
    {
        dim3 grid(N_PAD / 128, N_RELS);
        gemm_wmma_kernel<1><<<grid, 256, SMEM1>>>();
    }
    {
        long long threads = (long long)N_EDGES * 32;
        scatter_kernel<1><<<(unsigned)((threads + T - 1) / T), T>>>(etype, src, dst, norm, nullptr);
    }
    bias_relu_kernel<<<(N_NODES * 32 + T - 1) / T, T>>>(bias1);

    // ---- layer 2 ----
    zero_kernel<2><<<(N_NODES * OUT_DIM / 4 + T - 1) / T, T>>>(out);
    {
        dim3 grid(N_PAD / 128, N_RELS);
        gemm_wmma_kernel<2><<<grid, 256, SMEM2>>>();
    }
    {
        long long threads = (long long)N_EDGES * 32;
        scatter_kernel<2><<<(unsigned)((threads + T - 1) / T), T>>>(etype, src, dst, norm, out);
    }
    bias2_kernel<<<(N_NODES * 16 + T - 1) / T, T>>>(bias2, out);
}

// round 7
// speedup vs baseline: 2.5285x; 1.1562x over previous
#include <cuda_runtime.h>
#include <cuda_fp16.h>
#include <mma.h>
#include <cstdint>

using namespace nvcuda;

#define N_NODES 50000
#define N_PAD   50048   // 391 * 128 : full-tile padding for GEMM
#define N_EDGES 1000000
#define H_DIM   128
#define OUT_DIM 64
#define N_RELS  16

// ---------------- scratch (device globals; no runtime allocation) ----------------
__device__ __align__(256) __half g_Xh [N_PAD * H_DIM];               // fp16 x (pad rows BSS-zero, never written)
__device__ __align__(256) __half g_W1h[N_RELS * H_DIM * H_DIM];      // fp16 W1
__device__ __align__(256) __half g_W2h[N_RELS * H_DIM * OUT_DIM];    // fp16 W2
__device__ __align__(256) __half g_Y1h[(size_t)N_RELS * N_PAD * H_DIM];   // ~205 MB
__device__ __align__(256) __half g_Y2h[(size_t)N_RELS * N_PAD * OUT_DIM]; // ~102 MB
__device__ __align__(256) float  g_h1 [N_PAD * H_DIM];               // fp32 atomic target (pads BSS-zero)
__device__ __align__(256) __half g_h1h[N_PAD * H_DIM];               // fp16 copy for GEMM2 (pads BSS-zero)

// ---------------- small utility kernels ----------------
__global__ void gather_x_kernel(const int* __restrict__ ids,
                                const float* __restrict__ emb) {
    int i = blockIdx.x * blockDim.x + threadIdx.x;   // over N_NODES*16 uint4 (8 halves)
    if (i < N_NODES * 16) {
        int node = i >> 4;
        int c8   = i & 15;
        const float4* e4 = (const float4*)(emb + (size_t)ids[node] * H_DIM);
        float4 f0 = e4[c8 * 2], f1 = e4[c8 * 2 + 1];
        __half2 h[4];
        h[0] = __floats2half2_rn(f0.x, f0.y);
        h[1] = __floats2half2_rn(f0.z, f0.w);
        h[2] = __floats2half2_rn(f1.x, f1.y);
        h[3] = __floats2half2_rn(f1.z, f1.w);
        ((uint4*)g_Xh)[(size_t)node * 16 + c8] = *(uint4*)h;
    }
}

template <int OUTW>
__global__ void compute_W_kernel(const float* __restrict__ comp,
                                 const float* __restrict__ V) {
    const int sz = H_DIM * OUTW;
    int j = blockIdx.x * blockDim.x + threadIdx.x;
    int r = blockIdx.y;
    if (j < sz) {
        float acc = 0.f;
        #pragma unroll
        for (int b = 0; b < N_RELS; b++)
            acc += comp[r * N_RELS + b] * V[(size_t)b * sz + j];
        __half* Wh = (OUTW == H_DIM) ? g_W1h : g_W2h;
        Wh[(size_t)r * sz + j] = __float2half(acc);
    }
}

template <int LAYER>
__global__ void zero_kernel(float* __restrict__ out_ext) {
    const int n4 = (LAYER == 1) ? (N_NODES * H_DIM / 4) : (N_NODES * OUT_DIM / 4);
    float* p = (LAYER == 1) ? g_h1 : out_ext;
    int i = blockIdx.x * blockDim.x + threadIdx.x;
    if (i < n4)
        ((float4*)p)[i] = make_float4(0.f, 0.f, 0.f, 0.f);
}

// ---------------- wmma fp16 single-pass GEMM: Y[r] = A @ W[r] ----------------
// A (X or h1) fp16; W fp16; fp32 accumulate; Y stored fp16.
// Tile: BM=128, BN=(128|64), K=128 resident. 8 warps: 4(m) x 2(n).
template <int LAYER>
__global__ __launch_bounds__(256, 2) void gemm_wmma_kernel() {
    constexpr int BN = (LAYER == 1) ? 128 : 64;
    constexpr int AP = 136;           // A smem pitch (halves)
    constexpr int BP = BN + 8;        // B smem pitch (halves)
    constexpr int NF = BN / 2 / 16;   // n-frags per warp (4 | 2)
    constexpr int NU4 = BN / 8;       // uint4 per B row

    extern __shared__ __half sm[];
    __half* a_s = sm;
    __half* b_s = a_s + 128 * AP;

    const int tid = threadIdx.x;
    const int rel = blockIdx.y;
    const int m0  = blockIdx.x * 128;

    const __half* __restrict__ Ap = (LAYER == 1) ? g_Xh : g_h1h;
    const __half* __restrict__ Wh =
        ((LAYER == 1) ? g_W1h : g_W2h) + (size_t)rel * H_DIM * BN;
    __half* __restrict__ Yp =
        ((LAYER == 1) ? g_Y1h : g_Y2h) + (size_t)rel * N_PAD * BN;

    // ---- load A tile (always in bounds: N_PAD padding) ----
    #pragma unroll
    for (int i = tid; i < 128 * 16; i += 256) {
        int row = i >> 4, c8 = i & 15;
        *(uint4*)(a_s + row * AP + c8 * 8) =
            *(const uint4*)(Ap + (size_t)(m0 + row) * H_DIM + c8 * 8);
    }
    // ---- load B tile ----
    #pragma unroll
    for (int i = tid; i < 128 * NU4; i += 256) {
        int row = i / NU4, c = (i % NU4) * 8;
        *(uint4*)(b_s + row * BP + c) = *(const uint4*)(Wh + (size_t)row * BN + c);
    }
    __syncthreads();

    const int wid = tid >> 5;
    const int wm  = wid & 3;      // m offset wm*32
    const int wn  = wid >> 2;     // n offset wn*(BN/2)

    wmma::fragment<wmma::accumulator, 16, 16, 16, float> acc[2][NF];
    #pragma unroll
    for (int i = 0; i < 2; i++)
        #pragma unroll
        for (int j = 0; j < NF; j++)
            wmma::fill_fragment(acc[i][j], 0.f);

    #pragma unroll
    for (int k0 = 0; k0 < 128; k0 += 16) {
        wmma::fragment<wmma::matrix_a, 16, 16, 16, __half, wmma::row_major> af[2];
        #pragma unroll
        for (int i = 0; i < 2; i++)
            wmma::load_matrix_sync(af[i], a_s + (wm * 32 + i * 16) * AP + k0, AP);
        #pragma unroll
        for (int j = 0; j < NF; j++) {
            wmma::fragment<wmma::matrix_b, 16, 16, 16, __half, wmma::row_major> bf;
            wmma::load_matrix_sync(bf, b_s + k0 * BP + wn * (BN / 2) + j * 16, BP);
            #pragma unroll
            for (int i = 0; i < 2; i++)
                wmma::mma_sync(acc[i][j], af[i], bf, acc[i][j]);
        }
    }

    // ---- store fp16 (unguarded: N_PAD rows) ----
    #pragma unroll
    for (int i = 0; i < 2; i++)
        #pragma unroll
        for (int j = 0; j < NF; j++) {
            wmma::fragment<wmma::accumulator, 16, 16, 16, __half> hacc;
            #pragma unroll
            for (int e = 0; e < hacc.num_elements; e++)
                hacc.x[e] = __float2half(acc[i][j].x[e]);
            wmma::store_matrix_sync(
                Yp + (size_t)(m0 + wm * 32 + i * 16) * BN + wn * (BN / 2) + j * 16,
                hacc, BN, wmma::mem_row_major);
        }
}

// ---------------- edge scatter: out[dst] += norm * Y[etype, src] ----------------
__device__ __forceinline__ void red_add_v4(float* p, float4 v) {
    asm volatile("red.global.add.v4.f32 [%0], {%1, %2, %3, %4};"
                 :: "l"(p), "f"(v.x), "f"(v.y), "f"(v.z), "f"(v.w) : "memory");
}
__device__ __forceinline__ void red_add_v2(float* p, float2 v) {
    asm volatile("red.global.add.v2.f32 [%0], {%1, %2};"
                 :: "l"(p), "f"(v.x), "f"(v.y) : "memory");
}

template <int LAYER>
__global__ void scatter_kernel(const int* __restrict__ etype,
                               const int* __restrict__ src,
                               const int* __restrict__ dst,
                               const float* __restrict__ norm,
                               float* __restrict__ out_ext) {
    int e    = (blockIdx.x * blockDim.x + threadIdx.x) >> 5;
    int lane = threadIdx.x & 31;
    if (e >= N_EDGES) return;

    int   r  = etype[e];
    int   s  = src[e];
    int   d  = dst[e];
    float nm = norm[e];

    if (LAYER == 1) {
        uint2 v = ((const uint2*)(g_Y1h + ((size_t)r * N_PAD + s) * H_DIM))[lane];
        float2 f0 = __half22float2(*(__half2*)&v.x);
        float2 f1 = __half22float2(*(__half2*)&v.y);
        red_add_v4(g_h1 + (size_t)d * H_DIM + lane * 4,
                   make_float4(f0.x * nm, f0.y * nm, f1.x * nm, f1.y * nm));
    } else {
        uint32_t v = ((const uint32_t*)(g_Y2h + ((size_t)r * N_PAD + s) * OUT_DIM))[lane];
        float2 f = __half22float2(*(__half2*)&v);
        red_add_v2(out_ext + (size_t)d * OUT_DIM + lane * 2,
                   make_float2(f.x * nm, f.y * nm));
    }
}

// ---------------- epilogues ----------------
__global__ void bias_relu_kernel(const float* __restrict__ bias1) {
    int i = blockIdx.x * blockDim.x + threadIdx.x;  // over N_NODES*32 float4
    if (i < N_NODES * 32) {
        int c4 = i & 31;
        float4 v = ((float4*)g_h1)[i];
        const float4 b = ((const float4*)bias1)[c4];
        v.x = fmaxf(v.x + b.x, 0.f);
        v.y = fmaxf(v.y + b.y, 0.f);
        v.z = fmaxf(v.z + b.z, 0.f);
        v.w = fmaxf(v.w + b.w, 0.f);
        ((float4*)g_h1)[i] = v;
        __half2 h0 = __floats2half2_rn(v.x, v.y);
        __half2 h1v = __floats2half2_rn(v.z, v.w);
        ((uint2*)g_h1h)[i] = make_uint2(*(uint32_t*)&h0, *(uint32_t*)&h1v);
    }
}

__global__ void bias2_kernel(const float* __restrict__ bias2,
                             float* __restrict__ out_ext) {
    int i = blockIdx.x * blockDim.x + threadIdx.x;
    if (i < N_NODES * 16) {
        int c4 = i & 15;
        float4 v = ((float4*)out_ext)[i];
        const float4 b = ((const float4*)bias2)[c4];
        v.x += b.x; v.y += b.y; v.z += b.z; v.w += b.w;
        ((float4*)out_ext)[i] = v;
    }
}

// ---------------- launch ----------------
extern "C" void kernel_launch(void* const* d_in, const int* in_sizes, int n_in,
                              void* d_out, int out_size) {
    const int*   node_ids = (const int*)  d_in[0];
    const int*   src      = (const int*)  d_in[1];
    const int*   dst      = (const int*)  d_in[2];
    const int*   etype    = (const int*)  d_in[3];
    const float* norm     = (const float*)d_in[4];
    const float* emb      = (const float*)d_in[5];
    const float* V1       = (const float*)d_in[6];
    const float* comp1    = (const float*)d_in[7];
    const float* bias1    = (const float*)d_in[8];
    const float* V2       = (const float*)d_in[9];
    const float* comp2    = (const float*)d_in[10];
    const float* bias2    = (const float*)d_in[11];
    float*       out      = (float*)d_out;

    const int T = 256;
    // dyn smem (bytes): L1: (128*136 + 128*136)*2 = 69632 -> 3 CTA/SM
    //                   L2: (128*136 + 128*72)*2  = 53248 -> 4 CTA/SM
    const int SMEM1 = (128 * 136 + 128 * (128 + 8)) * 2;
    const int SMEM2 = (128 * 136 + 128 * (64 + 8)) * 2;
    cudaFuncSetAttribute(gemm_wmma_kernel<1>, cudaFuncAttributeMaxDynamicSharedMemorySize, SMEM1);
    cudaFuncSetAttribute(gemm_wmma_kernel<2>, cudaFuncAttributeMaxDynamicSharedMemorySize, SMEM2);

    // gather + fp16 convert X
    gather_x_kernel<<<(N_NODES * 16 + T - 1) / T, T>>>(node_ids, emb);

    // combine basis weights -> fp16
    {
        dim3 g1((H_DIM * H_DIM + T - 1) / T, N_RELS);
        compute_W_kernel<H_DIM><<<g1, T>>>(comp1, V1);
        dim3 g2((H_DIM * OUT_DIM + T - 1) / T, N_RELS);
        compute_W_kernel<OUT_DIM><<<g2, T>>>(comp2, V2);
    }

    // ---- layer 1 ----
    zero_kernel<1><<<(N_NODES * H_DIM / 4 + T - 1) / T, T>>>(nullptr);
    {
        dim3 grid(N_PAD / 128, N_RELS);
        gemm_wmma_kernel<1><<<grid, 256, SMEM1>>>();
    }
    {
        long long threads = (long long)N_EDGES * 32;
        scatter_kernel<1><<<(unsigned)((threads + T - 1) / T), T>>>(etype, src, dst, norm, nullptr);
    }
    bias_relu_kernel<<<(N_NODES * 32 + T - 1) / T, T>>>(bias1);

    // ---- layer 2 ----
    zero_kernel<2><<<(N_NODES * OUT_DIM / 4 + T - 1) / T, T>>>(out);
    {
        dim3 grid(N_PAD / 128, N_RELS);
        gemm_wmma_kernel<2><<<grid, 256, SMEM2>>>();
    }
    {
        long long threads = (long long)N_EDGES * 32;
        scatter_kernel<2><<<(unsigned)((threads + T - 1) / T), T>>>(etype, src, dst, norm, out);
    }
    bias2_kernel<<<(N_NODES * 16 + T - 1) / T, T>>>(bias2, out);
}